// round 6
// baseline (speedup 1.0000x reference)
#include <cuda_runtime.h>

// Fixed shapes
#define BATCH   262144
#define NIN     128
#define NMID    512
#define NCOLS   130                      // n_in + n_extra
#define GRID1   1024                     // one wave at 7 CTAs/SM (cap 1036)
#define ROWS_PER_BLK (BATCH / GRID1)     // 256

// Scratch (device globals; allocation forbidden)
__device__ __align__(16) float g_partial[(NIN + 1) * GRID1]; // [col][block]
__device__ __align__(16) float g_o[NIN];

// ---------------------------------------------------------------------------
// Pass 1: weighted column sums. 1024 blocks x 256 thr; launch_bounds(256,7)
// caps regs at 36 so all 1024 blocks are co-resident in ONE wave (7x148=1036).
// Warp owns 32 contiguous rows, 4 rows/iter with one float4 w-load.
// ---------------------------------------------------------------------------
__global__ void __launch_bounds__(256, 7)
reduce_pass(const float* __restrict__ x, const float* __restrict__ w) {
    const int tid = threadIdx.x;
    const int cg  = tid & 31;            // float4 column group
    const int wp  = tid >> 5;            // warp 0..7
    const int b   = blockIdx.x;
    const long rbase = (long)b * ROWS_PER_BLK + (long)wp * 32;

    const float4* x4 = reinterpret_cast<const float4*>(x) + rbase * 32 + cg;
    const float4* w4 = reinterpret_cast<const float4*>(w) + (rbase >> 2);

    float4 acc0 = make_float4(0.f, 0.f, 0.f, 0.f);
    float4 acc1 = make_float4(0.f, 0.f, 0.f, 0.f);
    float  wacc = 0.0f;

#pragma unroll
    for (int i = 0; i < 8; ++i) {        // 4 rows per iter, 32 rows total
        float4 wv = __ldg(w4 + i);
        float4 a  = __ldg(x4 + (4 * i + 0) * 32);
        float4 bb = __ldg(x4 + (4 * i + 1) * 32);
        float4 c  = __ldg(x4 + (4 * i + 2) * 32);
        float4 d  = __ldg(x4 + (4 * i + 3) * 32);
        acc0.x = fmaf(wv.x, a.x,  acc0.x); acc0.y = fmaf(wv.x, a.y,  acc0.y);
        acc0.z = fmaf(wv.x, a.z,  acc0.z); acc0.w = fmaf(wv.x, a.w,  acc0.w);
        acc1.x = fmaf(wv.y, bb.x, acc1.x); acc1.y = fmaf(wv.y, bb.y, acc1.y);
        acc1.z = fmaf(wv.y, bb.z, acc1.z); acc1.w = fmaf(wv.y, bb.w, acc1.w);
        acc0.x = fmaf(wv.z, c.x,  acc0.x); acc0.y = fmaf(wv.z, c.y,  acc0.y);
        acc0.z = fmaf(wv.z, c.z,  acc0.z); acc0.w = fmaf(wv.z, c.w,  acc0.w);
        acc1.x = fmaf(wv.w, d.x,  acc1.x); acc1.y = fmaf(wv.w, d.y,  acc1.y);
        acc1.z = fmaf(wv.w, d.z,  acc1.z); acc1.w = fmaf(wv.w, d.w,  acc1.w);
        wacc += (wv.x + wv.y) + (wv.z + wv.w);
    }
    acc0.x += acc1.x; acc0.y += acc1.y; acc0.z += acc1.z; acc0.w += acc1.w;

    __shared__ float s[8][NIN + 4];
    __shared__ float sw[8];
    s[wp][cg * 4 + 0] = acc0.x;
    s[wp][cg * 4 + 1] = acc0.y;
    s[wp][cg * 4 + 2] = acc0.z;
    s[wp][cg * 4 + 3] = acc0.w;
    if (cg == 0) sw[wp] = wacc;
    __syncthreads();

    if (tid < NIN) {
        float v = 0.0f;
#pragma unroll
        for (int l = 0; l < 8; ++l) v += s[l][tid];
        g_partial[tid * GRID1 + b] = v;
    } else if (tid == NIN) {
        float v = 0.0f;
#pragma unroll
        for (int l = 0; l < 8; ++l) v += sw[l];
        g_partial[NIN * GRID1 + b] = v;
    }
}

// ---------------------------------------------------------------------------
// Middle kernel: colsum -> xbar; v = relu(W_in @ xbar); o = W_out @ v.
// One block, 1024 threads (32 warps).
// Phase A: 4 threads per column -> 516 active threads, covers ALL 129 cols.
// ---------------------------------------------------------------------------
__global__ __launch_bounds__(1024) void mid_pass(const float* __restrict__ p,
                                                 const float* __restrict__ W_in,
                                                 const float* __restrict__ W_out) {
    __shared__ float part[(NIN + 1) * 4];
    __shared__ float colsum[NIN + 1];
    __shared__ float xbar[NCOLS];
    __shared__ float v[NMID];

    const int tid    = threadIdx.x;
    const int warpid = tid >> 5;
    const int lid    = tid & 31;

    // Phase A: column sums of g_partial (float4 loads, 4 threads per column)
    if (tid < (NIN + 1) * 4) {
        const int col = tid >> 2;        // 0..128
        const int k   = tid & 3;
        const float4* pp = reinterpret_cast<const float4*>(g_partial + col * GRID1);
        float4 s4 = make_float4(0.f, 0.f, 0.f, 0.f);
#pragma unroll 8
        for (int i = k; i < GRID1 / 4; i += 4) {
            float4 t = __ldg(pp + i);
            s4.x += t.x; s4.y += t.y; s4.z += t.z; s4.w += t.w;
        }
        part[tid] = (s4.x + s4.y) + (s4.z + s4.w);
    }
    __syncthreads();
    if (tid < NIN + 1)
        colsum[tid] = (part[tid * 4] + part[tid * 4 + 1]) + (part[tid * 4 + 2] + part[tid * 4 + 3]);
    __syncthreads();
    if (tid < NIN) {
        xbar[tid] = colsum[tid] / colsum[NIN];
    } else if (tid == NIN) {
        xbar[NIN]     = __ldg(p + 0);
        xbar[NIN + 1] = __ldg(p + 1);
    }
    __syncthreads();

    // Phase B: v[r] = relu(W_in[r,:] . xbar). 32 warps x 16 rows, 4 rows/step.
#pragma unroll
    for (int g = 0; g < 4; ++g) {
        const int r = warpid * 16 + g * 4;
        const float* w0 = W_in + (long)(r + 0) * NCOLS;
        const float* w1 = W_in + (long)(r + 1) * NCOLS;
        const float* w2 = W_in + (long)(r + 2) * NCOLS;
        const float* w3 = W_in + (long)(r + 3) * NCOLS;
        float a0 = 0.f, a1 = 0.f, a2 = 0.f, a3 = 0.f;
#pragma unroll
        for (int j = lid; j < NCOLS; j += 32) {
            const float xb = xbar[j];
            a0 = fmaf(__ldg(w0 + j), xb, a0);
            a1 = fmaf(__ldg(w1 + j), xb, a1);
            a2 = fmaf(__ldg(w2 + j), xb, a2);
            a3 = fmaf(__ldg(w3 + j), xb, a3);
        }
#pragma unroll
        for (int off = 16; off > 0; off >>= 1) {
            a0 += __shfl_xor_sync(0xffffffffu, a0, off);
            a1 += __shfl_xor_sync(0xffffffffu, a1, off);
            a2 += __shfl_xor_sync(0xffffffffu, a2, off);
            a3 += __shfl_xor_sync(0xffffffffu, a3, off);
        }
        if (lid == 0) {
            v[r + 0] = fmaxf(a0, 0.0f);
            v[r + 1] = fmaxf(a1, 0.0f);
            v[r + 2] = fmaxf(a2, 0.0f);
            v[r + 3] = fmaxf(a3, 0.0f);
        }
    }
    __syncthreads();

    // Phase C: g_o[c] = W_out[c,:] . v. 32 warps x 4 rows, 2 rows/step.
#pragma unroll
    for (int g = 0; g < 2; ++g) {
        const int c = warpid * 4 + g * 2;
        const float* w0 = W_out + (long)(c + 0) * NMID;
        const float* w1 = W_out + (long)(c + 1) * NMID;
        float a0 = 0.f, a1 = 0.f;
#pragma unroll
        for (int m = lid; m < NMID; m += 32) {
            const float vv = v[m];
            a0 = fmaf(__ldg(w0 + m), vv, a0);
            a1 = fmaf(__ldg(w1 + m), vv, a1);
        }
#pragma unroll
        for (int off = 16; off > 0; off >>= 1) {
            a0 += __shfl_xor_sync(0xffffffffu, a0, off);
            a1 += __shfl_xor_sync(0xffffffffu, a1, off);
        }
        if (lid == 0) {
            g_o[c + 0] = a0;
            g_o[c + 1] = a1;
        }
    }
}

// ---------------------------------------------------------------------------
// Pass 2: out = x + o. 1024 blocks x 256 thr x 32 float4 — mirrors reduce's
// 128KB slices, single wave at 7 CTAs/SM. Default-policy x reads (keep x
// L2-resident for the next graph replay's reduce); streaming stores for out.
// ---------------------------------------------------------------------------
__global__ void __launch_bounds__(256, 7)
add_pass(const float* __restrict__ x, float* __restrict__ out) {
    const int  tid  = threadIdx.x;
    const long base = (long)blockIdx.x * (256 * 32) + tid;

    const float4 ov = *(reinterpret_cast<const float4*>(g_o) + (tid & 31));
    const float4* x4 = reinterpret_cast<const float4*>(x);
    float4* o4p = reinterpret_cast<float4*>(out);

#pragma unroll
    for (int batch = 0; batch < 4; ++batch) {
        float4 r[8];
#pragma unroll
        for (int k = 0; k < 8; ++k)
            r[k] = __ldg(x4 + base + (long)(batch * 8 + k) * 256);
#pragma unroll
        for (int k = 0; k < 8; ++k) {
            r[k].x += ov.x; r[k].y += ov.y; r[k].z += ov.z; r[k].w += ov.w;
            __stcs(o4p + base + (long)(batch * 8 + k) * 256, r[k]);
        }
    }
}

// ---------------------------------------------------------------------------
extern "C" void kernel_launch(void* const* d_in, const int* in_sizes, int n_in,
                              void* d_out, int out_size) {
    const float* x     = (const float*)d_in[0];   // [262144,128]
    const float* w     = (const float*)d_in[1];   // [262144,1]
    const float* p     = (const float*)d_in[2];   // [1,2]
    const float* W_in  = (const float*)d_in[3];   // [512,130]
    const float* W_out = (const float*)d_in[4];   // [128,512]
    float* out = (float*)d_out;                   // [262144,128]

    reduce_pass<<<GRID1, 256>>>(x, w);
    mid_pass<<<1, 1024>>>(p, W_in, W_out);
    add_pass<<<GRID1, 256>>>(x, out);
}

// round 8
// speedup vs baseline: 1.0537x; 1.0537x over previous
#include <cuda_runtime.h>

// Fixed shapes
#define BATCH   262144
#define NIN     128
#define NMID    512
#define NCOLS   130                      // n_in + n_extra
#define GRID1   1024                     // one wave at 7 CTAs/SM (cap 1036)
#define ROWS_PER_BLK (BATCH / GRID1)     // 256

// Scratch (device globals; allocation forbidden)
__device__ __align__(16) float g_partial[(NIN + 1) * GRID1]; // [col][block]
__device__ __align__(16) float g_o[NIN];

// ---------------------------------------------------------------------------
// Pass 1: weighted column sums. 1024 blocks x 256 thr, launch_bounds(256,7)
// -> single wave. x is read with 256-bit L2::evict_last loads (the only legal
// width for that modifier on sm_103): fewer LDG issues, and x's tail stays
// L2-resident for add_pass (x=134MB vs L2=126MB -> ~94% resident).
// Warp covers 2 rows per load: sub=lane>>4 picks row, chunk=lane&15 the 32B.
// ---------------------------------------------------------------------------
__global__ void __launch_bounds__(256, 7)
reduce_pass(const float* __restrict__ x, const float* __restrict__ w) {
    const int tid   = threadIdx.x;
    const int lane  = tid & 31;
    const int wp    = tid >> 5;           // warp 0..7
    const int sub   = lane >> 4;          // row parity 0/1
    const int chunk = lane & 15;          // 32B chunk within 512B row
    const int b     = blockIdx.x;
    const long rbase = (long)b * ROWS_PER_BLK + (long)wp * 32;

    const float* xp = x + (rbase + sub) * NIN + chunk * 8;
    const float* wbase = w + rbase + sub;

    float acc[8];
#pragma unroll
    for (int j = 0; j < 8; ++j) acc[j] = 0.0f;
    float wacc = 0.0f;

#pragma unroll
    for (int i = 0; i < 16; ++i) {        // 2 rows per iter, 32 rows total
        unsigned r0, r1, r2, r3, r4, r5, r6, r7;
        asm volatile(
            "ld.global.nc.L2::evict_last.v8.b32 {%0,%1,%2,%3,%4,%5,%6,%7}, [%8];"
            : "=r"(r0), "=r"(r1), "=r"(r2), "=r"(r3),
              "=r"(r4), "=r"(r5), "=r"(r6), "=r"(r7)
            : "l"(xp + (long)(2 * i) * NIN));
        const float wv = __ldg(wbase + 2 * i);
        acc[0] = fmaf(wv, __uint_as_float(r0), acc[0]);
        acc[1] = fmaf(wv, __uint_as_float(r1), acc[1]);
        acc[2] = fmaf(wv, __uint_as_float(r2), acc[2]);
        acc[3] = fmaf(wv, __uint_as_float(r3), acc[3]);
        acc[4] = fmaf(wv, __uint_as_float(r4), acc[4]);
        acc[5] = fmaf(wv, __uint_as_float(r5), acc[5]);
        acc[6] = fmaf(wv, __uint_as_float(r6), acc[6]);
        acc[7] = fmaf(wv, __uint_as_float(r7), acc[7]);
        wacc += wv;
    }

    // fold the two row-parity halves (lanes L and L+16 hold the SAME columns)
#pragma unroll
    for (int j = 0; j < 8; ++j)
        acc[j] += __shfl_xor_sync(0xffffffffu, acc[j], 16);
    wacc += __shfl_xor_sync(0xffffffffu, wacc, 16);

    __shared__ float s[8][NIN + 4];
    __shared__ float sw[8];
    if (sub == 0) {
#pragma unroll
        for (int j = 0; j < 8; ++j) s[wp][chunk * 8 + j] = acc[j];
        if (chunk == 0) sw[wp] = wacc;
    }
    __syncthreads();

    if (tid < NIN) {
        float v = 0.0f;
#pragma unroll
        for (int l = 0; l < 8; ++l) v += s[l][tid];
        g_partial[tid * GRID1 + b] = v;
    } else if (tid == NIN) {
        float v = 0.0f;
#pragma unroll
        for (int l = 0; l < 8; ++l) v += sw[l];
        g_partial[NIN * GRID1 + b] = v;
    }
}

// ---------------------------------------------------------------------------
// Middle kernel: colsum -> xbar; v = relu(W_in @ xbar); o = W_out @ v.
// One block, 1024 threads. Phase A: 4 thr/col covers ALL 129 columns.
// ---------------------------------------------------------------------------
__global__ __launch_bounds__(1024) void mid_pass(const float* __restrict__ p,
                                                 const float* __restrict__ W_in,
                                                 const float* __restrict__ W_out) {
    __shared__ float part[(NIN + 1) * 4];
    __shared__ float colsum[NIN + 1];
    __shared__ float xbar[NCOLS];
    __shared__ float v[NMID];

    const int tid    = threadIdx.x;
    const int warpid = tid >> 5;
    const int lid    = tid & 31;

    if (tid < (NIN + 1) * 4) {
        const int col = tid >> 2;        // 0..128
        const int k   = tid & 3;
        const float4* pp = reinterpret_cast<const float4*>(g_partial + col * GRID1);
        float4 s4 = make_float4(0.f, 0.f, 0.f, 0.f);
#pragma unroll 8
        for (int i = k; i < GRID1 / 4; i += 4) {
            float4 t = __ldg(pp + i);
            s4.x += t.x; s4.y += t.y; s4.z += t.z; s4.w += t.w;
        }
        part[tid] = (s4.x + s4.y) + (s4.z + s4.w);
    }
    __syncthreads();
    if (tid < NIN + 1)
        colsum[tid] = (part[tid * 4] + part[tid * 4 + 1]) + (part[tid * 4 + 2] + part[tid * 4 + 3]);
    __syncthreads();
    if (tid < NIN) {
        xbar[tid] = colsum[tid] / colsum[NIN];
    } else if (tid == NIN) {
        xbar[NIN]     = __ldg(p + 0);
        xbar[NIN + 1] = __ldg(p + 1);
    }
    __syncthreads();

#pragma unroll
    for (int g = 0; g < 4; ++g) {
        const int r = warpid * 16 + g * 4;
        const float* w0 = W_in + (long)(r + 0) * NCOLS;
        const float* w1 = W_in + (long)(r + 1) * NCOLS;
        const float* w2 = W_in + (long)(r + 2) * NCOLS;
        const float* w3 = W_in + (long)(r + 3) * NCOLS;
        float a0 = 0.f, a1 = 0.f, a2 = 0.f, a3 = 0.f;
#pragma unroll
        for (int j = lid; j < NCOLS; j += 32) {
            const float xb = xbar[j];
            a0 = fmaf(__ldg(w0 + j), xb, a0);
            a1 = fmaf(__ldg(w1 + j), xb, a1);
            a2 = fmaf(__ldg(w2 + j), xb, a2);
            a3 = fmaf(__ldg(w3 + j), xb, a3);
        }
#pragma unroll
        for (int off = 16; off > 0; off >>= 1) {
            a0 += __shfl_xor_sync(0xffffffffu, a0, off);
            a1 += __shfl_xor_sync(0xffffffffu, a1, off);
            a2 += __shfl_xor_sync(0xffffffffu, a2, off);
            a3 += __shfl_xor_sync(0xffffffffu, a3, off);
        }
        if (lid == 0) {
            v[r + 0] = fmaxf(a0, 0.0f);
            v[r + 1] = fmaxf(a1, 0.0f);
            v[r + 2] = fmaxf(a2, 0.0f);
            v[r + 3] = fmaxf(a3, 0.0f);
        }
    }
    __syncthreads();

#pragma unroll
    for (int g = 0; g < 2; ++g) {
        const int c = warpid * 4 + g * 2;
        const float* w0 = W_out + (long)(c + 0) * NMID;
        const float* w1 = W_out + (long)(c + 1) * NMID;
        float a0 = 0.f, a1 = 0.f;
#pragma unroll
        for (int m = lid; m < NMID; m += 32) {
            const float vv = v[m];
            a0 = fmaf(__ldg(w0 + m), vv, a0);
            a1 = fmaf(__ldg(w1 + m), vv, a1);
        }
#pragma unroll
        for (int off = 16; off > 0; off >>= 1) {
            a0 += __shfl_xor_sync(0xffffffffu, a0, off);
            a1 += __shfl_xor_sync(0xffffffffu, a1, off);
        }
        if (lid == 0) {
            g_o[c + 0] = a0;
            g_o[c + 1] = a1;
        }
    }
}

// ---------------------------------------------------------------------------
// Pass 2: out = x + o. 4096 blocks x 256 thr x 8 float4 (32KB per block).
// Each reduce slice (128KB) = 4 add sub-blocks, consumed TAIL-FIRST across
// scheduling groups so L2-resident (evict_last) x is read before eviction.
// __ldcs: consumed x lines become evict-first victims; __stcs: out stream
// preferentially displaces those, not unread x.
// ---------------------------------------------------------------------------
#define ADD_BLOCKS   4096
#define F4_PER_BLOCK 2048                // 256 threads * 8

__global__ void __launch_bounds__(256)
add_pass(const float* __restrict__ x, float* __restrict__ out) {
    const int tid = threadIdx.x;
    const int beta  = blockIdx.x;
    const int slice = beta & 1023;           // 0..1023
    const int sub   = 3 - (beta >> 10);      // 3..0 (tail-first)
    const long blk  = (long)slice * 4 + sub;
    const long base = blk * F4_PER_BLOCK + tid;

    const float4 ov = *(reinterpret_cast<const float4*>(g_o) + (tid & 31));
    const float4* x4 = reinterpret_cast<const float4*>(x);
    float4* o4p = reinterpret_cast<float4*>(out);

    float4 r[8];
#pragma unroll
    for (int k = 0; k < 8; ++k)
        r[k] = __ldcs(x4 + base + (long)k * 256);
#pragma unroll
    for (int k = 0; k < 8; ++k) {
        r[k].x += ov.x; r[k].y += ov.y; r[k].z += ov.z; r[k].w += ov.w;
        __stcs(o4p + base + (long)k * 256, r[k]);
    }
}

// ---------------------------------------------------------------------------
extern "C" void kernel_launch(void* const* d_in, const int* in_sizes, int n_in,
                              void* d_out, int out_size) {
    const float* x     = (const float*)d_in[0];   // [262144,128]
    const float* w     = (const float*)d_in[1];   // [262144,1]
    const float* p     = (const float*)d_in[2];   // [1,2]
    const float* W_in  = (const float*)d_in[3];   // [512,130]
    const float* W_out = (const float*)d_in[4];   // [128,512]
    float* out = (float*)d_out;                   // [262144,128]

    reduce_pass<<<GRID1, 256>>>(x, w);
    mid_pass<<<1, 1024>>>(p, W_in, W_out);
    add_pass<<<ADD_BLOCKS, 256>>>(x, out);
}